// round 16
// baseline (speedup 1.0000x reference)
#include <cuda_runtime.h>
#include <cuda_bf16.h>
#include <cstdint>
#include <math.h>

#define NPTS 50000
#define KNB  16
#define HALF 64
#define DIM  128
#define TILES8 (NPTS / 8)        // 6250
#define RSF   144                // W smem row stride in floats (128 + 16 pad)

// ---------------- scratch (__device__ globals; no allocs allowed) -------
__device__ float g_p0[NPTS * HALF];
__device__ float g_p1[NPTS * HALF];
__device__ float g_u [NPTS * DIM];   // p1 @ W3a_top
__device__ float g_cc[NPTS * DIM];   // b3a - u + p_local @ W3a_bot
__device__ unsigned int g_tileCtr;   // dynamic tile scheduler (reset by k_uc)

// ---------------- k_mlp smem map (bytes) ----------------
#define OFF_WB 0                 // 128 * 144 * 4 = 73728
#define OFF_BB 73728             // 512
#define SMEM_BYTES 74240

#define UC_SMEM_BYTES 75264

// ---------------- helpers ----------------
static __device__ __forceinline__ void mma_tf32(float* d,
    uint32_t a0, uint32_t a1, uint32_t a2, uint32_t a3, uint32_t b0, uint32_t b1) {
    asm volatile("mma.sync.aligned.m16n8k8.row.col.f32.tf32.tf32.f32 "
        "{%0,%1,%2,%3}, {%4,%5,%6,%7}, {%8,%9}, {%0,%1,%2,%3};"
        : "+f"(d[0]), "+f"(d[1]), "+f"(d[2]), "+f"(d[3])
        : "r"(a0), "r"(a1), "r"(a2), "r"(a3), "r"(b0), "r"(b1));
}
static __device__ __forceinline__ uint32_t to_tf32(float x) {
    uint32_t r;
    asm("cvt.rna.tf32.f32 %0, %1;" : "=r"(r) : "f"(x));
    return r;
}
// branch-free gelu via A&S 7.1.26 erfc, constants pre-folded (|eps|<=1.5e-7)
static __device__ __forceinline__ float gelu_fast(float x) {
    float x2 = x * x;
    float den = fmaf(fabsf(x), 0.23173867f, 1.0f);   // p/sqrt(2)
    float t;
    asm("rcp.approx.f32 %0, %1;" : "=f"(t) : "f"(den));
    float q = t * fmaf(t, fmaf(t, fmaf(t, fmaf(t, 0.5307027145f, -0.7265760135f),
                                       0.7107068705f), -0.142248368f), 0.127414796f);
    float ex;
    asm("ex2.approx.f32 %0, %1;" : "=f"(ex) : "f"(x2 * -0.72134752f));  // -1/(2 ln2)
    float E  = q * ex;
    float xe = x * E;
    return (x >= 0.f) ? (x - xe) : xe;
}

// ---------------- kernel 1: p0 = xyz@W1+b1 ; p1 = p0@W2+b2 ----------------
__global__ void __launch_bounds__(256)
k_p01(const float* __restrict__ xyz, const float* __restrict__ W1,
      const float* __restrict__ b1, const float* __restrict__ W2,
      const float* __restrict__ b2) {
    __shared__ float sp0[16][HALF];
    const int tid  = threadIdx.x;
    const int base = blockIdx.x * 16;

    for (int t = tid; t < 16 * HALF; t += 256) {
        int p = t >> 6, c = t & 63;
        int i = base + p;
        float x = __ldg(&xyz[i * 3 + 0]);
        float y = __ldg(&xyz[i * 3 + 1]);
        float z = __ldg(&xyz[i * 3 + 2]);
        float v = fmaf(z, __ldg(&W1[2 * HALF + c]), __ldg(&b1[c]));
        v = fmaf(y, __ldg(&W1[1 * HALF + c]), v);
        v = fmaf(x, __ldg(&W1[0 * HALF + c]), v);
        g_p0[i * HALF + c] = v;
        sp0[p][c] = v;
    }
    __syncthreads();

    const int c  = tid & 63;
    const int p0i = (tid >> 6) * 4;
    float bb = __ldg(&b2[c]);
    float a0 = bb, a1 = bb, a2 = bb, a3 = bb;
#pragma unroll 8
    for (int e = 0; e < HALF; e++) {
        float w = __ldg(&W2[e * HALF + c]);
        a0 = fmaf(sp0[p0i + 0][e], w, a0);
        a1 = fmaf(sp0[p0i + 1][e], w, a1);
        a2 = fmaf(sp0[p0i + 2][e], w, a2);
        a3 = fmaf(sp0[p0i + 3][e], w, a3);
    }
    g_p1[(base + p0i + 0) * HALF + c] = a0;
    g_p1[(base + p0i + 1) * HALF + c] = a1;
    g_p1[(base + p0i + 2) * HALF + c] = a2;
    g_p1[(base + p0i + 3) * HALF + c] = a3;
}

// ---------------- kernel 2: fused p_local + (u, cc) --------------------
__global__ void __launch_bounds__(256)
k_uc(const int* __restrict__ knn, const float* __restrict__ W3a,
     const float* __restrict__ b3a) {
    extern __shared__ float us[];
    float* sW   = us;              // 16384
    float* sp1  = us + 16384;      // 16 x 64
    float* spl  = sp1 + 1024;      // 16 x 64
    float* sb   = spl + 1024;      // 128
    int*   sknn = (int*)(sb + 128);// 256

    const int tid  = threadIdx.x;
    const int base = blockIdx.x * 16;

    // reset the k_mlp tile scheduler for this launch (k_mlp's steals happen
    // only after its grid-dep sync on this kernel's completion)
    if (blockIdx.x == 0 && tid == 0) g_tileCtr = 0u;

    // prologue: inputs only (runs under PDL overlap)
    for (int t = tid; t < 16384; t += 256) sW[t] = __ldg(&W3a[t]);
    if (tid < 128) sb[tid] = __ldg(&b3a[tid]);
    sknn[tid] = __ldg(&knn[base * KNB + tid]);

    cudaGridDependencySynchronize();   // wait for k_p01's writes

    for (int t = tid; t < 1024; t += 256) {
        int p = t >> 6, e = t & 63;
        sp1[t] = g_p1[(base + p) * HALF + e];
    }
    __syncthreads();

    for (int t = tid; t < 1024; t += 256) {
        int p = t >> 6, c = t & 63;
        float own = g_p0[(base + p) * HALF + c];
        float m = -3.402823466e38f;
#pragma unroll
        for (int k = 0; k < KNB; k++) {
            int j = sknn[p * KNB + k];
            m = fmaxf(m, __ldg(&g_p0[j * HALF + c]) - own);
        }
        spl[t] = m;
    }
    __syncthreads();

    const int c  = tid & 127;
    const int ph = (tid >> 7) * 8;
    float aU[8], aC[8];
#pragma unroll
    for (int pp = 0; pp < 8; pp++) { aU[pp] = 0.f; aC[pp] = sb[c]; }
#pragma unroll 8
    for (int e = 0; e < HALF; e++) {
        float w1 = sW[e * DIM + c];
        float w2 = sW[(HALF + e) * DIM + c];
#pragma unroll
        for (int pp = 0; pp < 8; pp++) {
            aU[pp] = fmaf(sp1[(ph + pp) * HALF + e], w1, aU[pp]);
            aC[pp] = fmaf(spl[(ph + pp) * HALF + e], w2, aC[pp]);
        }
    }
#pragma unroll
    for (int pp = 0; pp < 8; pp++) {
        size_t idx = (size_t)(base + ph + pp) * DIM + c;
        g_u[idx]  = aU[pp];
        g_cc[idx] = aC[pp] - aU[pp];
    }
}

// ---------------- kernel 3: gather+GELU -> tf32 GEMM2 --------------------
// B operands double-buffered in registers (LDS issued 2 n-tiles ahead,
// wrap-invariant across ks and tiles). Tiles 0..grid-1 static, remainder
// via a SINGLE CTA-level atomic steal per tile (round-15 bug: per-warp
// steals dropped 7/8 of grabbed tiles).
__global__ void __launch_bounds__(256, 2)
k_mlp(const int* __restrict__ knn,
      const float* __restrict__ W3b, const float* __restrict__ b3b,
      float* __restrict__ out) {
    extern __shared__ char smem[];
    float* sW  = (float*)(smem + OFF_WB);
    float* sBb = (float*)(smem + OFF_BB);
    __shared__ int s_next;
    const int tid  = threadIdx.x;
    const int wid  = tid >> 5;
    const int lane = tid & 31;

    // prologue: inputs only (runs under PDL overlap)
    for (int idx = tid; idx < 16384; idx += 256) {
        int k = idx >> 7, n = idx & 127;
        uint32_t v = to_tf32(__ldg(&W3b[k * DIM + n]));
        sW[n * RSF + k] = __uint_as_float(v);
    }
    if (tid < 128) sBb[tid] = __ldg(&b3b[tid]);
    __syncthreads();

    const int qr = lane >> 2;            // fragment row group (0..7)
    const int qc = (lane & 3) * 2;       // output col pair in n8-tile
    const int q4 = (lane & 3) * 4;       // contiguous k base
    const float* wB = sW + (size_t)qr * RSF + q4;

    int tile = blockIdx.x;               // first tile static
    int jj = __ldg(&knn[(tile * 8 + wid) * KNB + (lane & 15)]);

    cudaGridDependencySynchronize();     // wait for k_uc's g_u/g_cc writes

    const float* u0;
    const float* u1;
    const float* cp;
    {
        const int j0 = __shfl_sync(0xFFFFFFFF, jj, qr);
        const int j1 = __shfl_sync(0xFFFFFFFF, jj, qr + 8);
        u0 = g_u  + (size_t)j0 * DIM + q4;
        u1 = g_u  + (size_t)j1 * DIM + q4;
        cp = g_cc + (size_t)(tile * 8 + wid) * DIM + q4;
    }
    float4 va = *(const float4*)(u0);
    float4 vb = *(const float4*)(u1);
    float4 vc = *(const float4*)(cp);

    // rolling B double-buffer: nt0, nt1 of ks0 (self-sustaining across tiles)
    float4 w0 = *(const float4*)(wB);
    float4 w1 = *(const float4*)(wB + 8 * RSF);

    while (true) {
        const int i = tile * 8 + wid;

        // one CTA-level steal per tile; barrier 1 retires the previous read,
        // barrier 2 publishes the new value
        __syncthreads();
        if (tid == 0) s_next = (int)(gridDim.x + atomicAdd(&g_tileCtr, 1u));
        __syncthreads();
        const int tnext = s_next;

        int jjn = 0;
        if (tnext < TILES8) jjn = __ldg(&knn[(tnext * 8 + wid) * KNB + (lane & 15)]);

        float acc[16][4];
#pragma unroll
        for (int t = 0; t < 16; t++) { acc[t][0] = acc[t][1] = acc[t][2] = acc[t][3] = 0.f; }

#pragma unroll
        for (int ks = 0; ks < 8; ks++) {
            float4 na, nb, nc;
            if (ks < 7) {
                const int kb = (ks + 1) * 16;
                na = *(const float4*)(u0 + kb);
                nb = *(const float4*)(u1 + kb);
                nc = *(const float4*)(cp + kb);
            } else {
                const int j0n = __shfl_sync(0xFFFFFFFF, jjn, qr);
                const int j1n = __shfl_sync(0xFFFFFFFF, jjn, qr + 8);
                const int inext = (tnext < TILES8) ? (tnext * 8 + wid) : 0;
                u0 = g_u  + (size_t)j0n * DIM + q4;
                u1 = g_u  + (size_t)j1n * DIM + q4;
                cp = g_cc + (size_t)inext * DIM + q4;
                na = *(const float4*)(u0);
                nb = *(const float4*)(u1);
                nc = *(const float4*)(cp);
            }

            // h = gelu(u + cc) for data-k {4c..4c+3}, rows j0 / j1
            uint32_t a00 = to_tf32(gelu_fast(va.x + vc.x));
            uint32_t a01 = to_tf32(gelu_fast(va.y + vc.y));
            uint32_t a02 = to_tf32(gelu_fast(va.z + vc.z));
            uint32_t a03 = to_tf32(gelu_fast(va.w + vc.w));
            uint32_t a10 = to_tf32(gelu_fast(vb.x + vc.x));
            uint32_t a11 = to_tf32(gelu_fast(vb.y + vc.y));
            uint32_t a12 = to_tf32(gelu_fast(vb.z + vc.z));
            uint32_t a13 = to_tf32(gelu_fast(vb.w + vc.w));

            const float* wk  = wB + ks * 16;
            const float* wkn = wB + ((ks + 1) & 7) * 16;   // wraps across tiles too
#pragma unroll
            for (int nt = 0; nt < 16; nt++) {
                float4 wn = (nt < 14)
                    ? *(const float4*)(wk  + (size_t)(nt + 2) * 8 * RSF)
                    : *(const float4*)(wkn + (size_t)(nt - 14) * 8 * RSF);
                mma_tf32(acc[nt], a00, a10, a01, a11,
                         __float_as_uint(w0.x), __float_as_uint(w0.y));
                mma_tf32(acc[nt], a02, a12, a03, a13,
                         __float_as_uint(w0.z), __float_as_uint(w0.w));
                w0 = w1; w1 = wn;
            }
            va = na; vb = nb; vc = nc;
        }

        // ---- epilogue: +b3b, store ----
        {
            float* obase = out + ((size_t)i * KNB) * DIM;
#pragma unroll
            for (int nt = 0; nt < 16; nt++) {
                int c = nt * 8 + qc;
                float bb0 = sBb[c], bb1 = sBb[c + 1];
                *(float2*)(obase + (size_t)qr * DIM + c) =
                    make_float2(acc[nt][0] + bb0, acc[nt][1] + bb1);
                *(float2*)(obase + (size_t)(qr + 8) * DIM + c) =
                    make_float2(acc[nt][2] + bb0, acc[nt][3] + bb1);
            }
        }
        jj = jjn;
        if (tnext >= TILES8) break;
        tile = tnext;
    }
}

// ---------------- launch ----------------
extern "C" void kernel_launch(void* const* d_in, const int* in_sizes, int n_in,
                              void* d_out, int out_size) {
    const float* xyz = (const float*)d_in[0];
    const int*   knn = (const int*)d_in[1];
    const float* W1  = (const float*)d_in[2];
    const float* b1  = (const float*)d_in[3];
    const float* W2  = (const float*)d_in[4];
    const float* b2  = (const float*)d_in[5];
    const float* W3a = (const float*)d_in[6];
    const float* b3a = (const float*)d_in[7];
    const float* W3b = (const float*)d_in[8];
    const float* b3b = (const float*)d_in[9];
    float* out = (float*)d_out;

    cudaFuncSetAttribute(k_uc, cudaFuncAttributeMaxDynamicSharedMemorySize, UC_SMEM_BYTES);
    cudaFuncSetAttribute(k_mlp, cudaFuncAttributeMaxDynamicSharedMemorySize, SMEM_BYTES);

    int dev = 0, sms = 148;
    cudaGetDevice(&dev);
    cudaDeviceGetAttribute(&sms, cudaDevAttrMultiProcessorCount, dev);

    k_p01<<<NPTS / 16, 256>>>(xyz, W1, b1, W2, b2);

    cudaLaunchAttribute attr[1];
    attr[0].id = cudaLaunchAttributeProgrammaticStreamSerialization;
    attr[0].val.programmaticStreamSerializationAllowed = 1;

    {   // k_uc with PDL (prologue overlaps k_p01 tail)
        cudaLaunchConfig_t cfg = {};
        cfg.gridDim = dim3(NPTS / 16, 1, 1);
        cfg.blockDim = dim3(256, 1, 1);
        cfg.dynamicSmemBytes = UC_SMEM_BYTES;
        cfg.stream = 0;
        cfg.attrs = attr;
        cfg.numAttrs = 1;
        cudaLaunchKernelEx(&cfg, k_uc, knn, W3a, b3a);
    }
    {   // k_mlp with PDL (W transpose overlaps k_uc tail)
        cudaLaunchConfig_t cfg = {};
        cfg.gridDim = dim3(2 * sms, 1, 1);
        cfg.blockDim = dim3(256, 1, 1);
        cfg.dynamicSmemBytes = SMEM_BYTES;
        cfg.stream = 0;
        cfg.attrs = attr;
        cfg.numAttrs = 1;
        cudaLaunchKernelEx(&cfg, k_mlp, knn, W3b, b3b, out);
    }
}

// round 17
// speedup vs baseline: 1.1528x; 1.1528x over previous
#include <cuda_runtime.h>
#include <cuda_bf16.h>
#include <cstdint>
#include <math.h>

#define NPTS 50000
#define KNB  16
#define HALF 64
#define DIM  128
#define RSF   144                // W smem row stride in floats (128 + 16 pad)

// ---------------- scratch (__device__ globals; no allocs allowed) -------
__device__ float g_p0[NPTS * HALF];
__device__ float g_p1[NPTS * HALF];
__device__ float g_u [NPTS * DIM];   // p1 @ W3a_top
__device__ float g_cc[NPTS * DIM];   // b3a - u + p_local @ W3a_bot
__device__ unsigned int g_ptCtr;     // per-warp point scheduler (reset by k_uc)

// ---------------- k_mlp smem map (bytes) ----------------
#define OFF_WB 0                 // 128 * 144 * 4 = 73728
#define OFF_BB 73728             // 512
#define SMEM_BYTES 74240

#define UC_SMEM_BYTES 75264

// ---------------- helpers ----------------
static __device__ __forceinline__ void mma_tf32(float* d,
    uint32_t a0, uint32_t a1, uint32_t a2, uint32_t a3, uint32_t b0, uint32_t b1) {
    asm volatile("mma.sync.aligned.m16n8k8.row.col.f32.tf32.tf32.f32 "
        "{%0,%1,%2,%3}, {%4,%5,%6,%7}, {%8,%9}, {%0,%1,%2,%3};"
        : "+f"(d[0]), "+f"(d[1]), "+f"(d[2]), "+f"(d[3])
        : "r"(a0), "r"(a1), "r"(a2), "r"(a3), "r"(b0), "r"(b1));
}
static __device__ __forceinline__ uint32_t to_tf32(float x) {
    uint32_t r;
    asm("cvt.rna.tf32.f32 %0, %1;" : "=r"(r) : "f"(x));
    return r;
}
// branch-free gelu via A&S 7.1.26 erfc, constants pre-folded (|eps|<=1.5e-7)
static __device__ __forceinline__ float gelu_fast(float x) {
    float x2 = x * x;
    float den = fmaf(fabsf(x), 0.23173867f, 1.0f);   // p/sqrt(2)
    float t;
    asm("rcp.approx.f32 %0, %1;" : "=f"(t) : "f"(den));
    float q = t * fmaf(t, fmaf(t, fmaf(t, fmaf(t, 0.5307027145f, -0.7265760135f),
                                       0.7107068705f), -0.142248368f), 0.127414796f);
    float ex;
    asm("ex2.approx.f32 %0, %1;" : "=f"(ex) : "f"(x2 * -0.72134752f));  // -1/(2 ln2)
    float E  = q * ex;
    float xe = x * E;
    return (x >= 0.f) ? (x - xe) : xe;
}

// ---------------- kernel 1: p0 = xyz@W1+b1 ; p1 = p0@W2+b2 ----------------
__global__ void __launch_bounds__(256)
k_p01(const float* __restrict__ xyz, const float* __restrict__ W1,
      const float* __restrict__ b1, const float* __restrict__ W2,
      const float* __restrict__ b2) {
    __shared__ float sp0[16][HALF];
    const int tid  = threadIdx.x;
    const int base = blockIdx.x * 16;

    for (int t = tid; t < 16 * HALF; t += 256) {
        int p = t >> 6, c = t & 63;
        int i = base + p;
        float x = __ldg(&xyz[i * 3 + 0]);
        float y = __ldg(&xyz[i * 3 + 1]);
        float z = __ldg(&xyz[i * 3 + 2]);
        float v = fmaf(z, __ldg(&W1[2 * HALF + c]), __ldg(&b1[c]));
        v = fmaf(y, __ldg(&W1[1 * HALF + c]), v);
        v = fmaf(x, __ldg(&W1[0 * HALF + c]), v);
        g_p0[i * HALF + c] = v;
        sp0[p][c] = v;
    }
    __syncthreads();

    const int c  = tid & 63;
    const int p0i = (tid >> 6) * 4;
    float bb = __ldg(&b2[c]);
    float a0 = bb, a1 = bb, a2 = bb, a3 = bb;
#pragma unroll 8
    for (int e = 0; e < HALF; e++) {
        float w = __ldg(&W2[e * HALF + c]);
        a0 = fmaf(sp0[p0i + 0][e], w, a0);
        a1 = fmaf(sp0[p0i + 1][e], w, a1);
        a2 = fmaf(sp0[p0i + 2][e], w, a2);
        a3 = fmaf(sp0[p0i + 3][e], w, a3);
    }
    g_p1[(base + p0i + 0) * HALF + c] = a0;
    g_p1[(base + p0i + 1) * HALF + c] = a1;
    g_p1[(base + p0i + 2) * HALF + c] = a2;
    g_p1[(base + p0i + 3) * HALF + c] = a3;
}

// ---------------- kernel 2: fused p_local + (u, cc) --------------------
__global__ void __launch_bounds__(256)
k_uc(const int* __restrict__ knn, const float* __restrict__ W3a,
     const float* __restrict__ b3a) {
    extern __shared__ float us[];
    float* sW   = us;              // 16384
    float* sp1  = us + 16384;      // 16 x 64
    float* spl  = sp1 + 1024;      // 16 x 64
    float* sb   = spl + 1024;      // 128
    int*   sknn = (int*)(sb + 128);// 256

    const int tid  = threadIdx.x;
    const int base = blockIdx.x * 16;

    // reset the k_mlp point scheduler (k_mlp steals only after its grid-dep
    // sync on this kernel, so ordering is guaranteed by the PDL chain)
    if (blockIdx.x == 0 && tid == 0) g_ptCtr = 0u;

    // prologue: inputs only (runs under PDL overlap)
    for (int t = tid; t < 16384; t += 256) sW[t] = __ldg(&W3a[t]);
    if (tid < 128) sb[tid] = __ldg(&b3a[tid]);
    sknn[tid] = __ldg(&knn[base * KNB + tid]);

    cudaGridDependencySynchronize();   // wait for k_p01's writes

    for (int t = tid; t < 1024; t += 256) {
        int p = t >> 6, e = t & 63;
        sp1[t] = g_p1[(base + p) * HALF + e];
    }
    __syncthreads();

    for (int t = tid; t < 1024; t += 256) {
        int p = t >> 6, c = t & 63;
        float own = g_p0[(base + p) * HALF + c];
        float m = -3.402823466e38f;
#pragma unroll
        for (int k = 0; k < KNB; k++) {
            int j = sknn[p * KNB + k];
            m = fmaxf(m, __ldg(&g_p0[j * HALF + c]) - own);
        }
        spl[t] = m;
    }
    __syncthreads();

    const int c  = tid & 127;
    const int ph = (tid >> 7) * 8;
    float aU[8], aC[8];
#pragma unroll
    for (int pp = 0; pp < 8; pp++) { aU[pp] = 0.f; aC[pp] = sb[c]; }
#pragma unroll 8
    for (int e = 0; e < HALF; e++) {
        float w1 = sW[e * DIM + c];
        float w2 = sW[(HALF + e) * DIM + c];
#pragma unroll
        for (int pp = 0; pp < 8; pp++) {
            aU[pp] = fmaf(sp1[(ph + pp) * HALF + e], w1, aU[pp]);
            aC[pp] = fmaf(spl[(ph + pp) * HALF + e], w2, aC[pp]);
        }
    }
#pragma unroll
    for (int pp = 0; pp < 8; pp++) {
        size_t idx = (size_t)(base + ph + pp) * DIM + c;
        g_u[idx]  = aU[pp];
        g_cc[idx] = aC[pp] - aU[pp];
    }
}

// ---------------- kernel 3: gather+GELU -> tf32 GEMM2 --------------------
// Work unit = ONE POINT PER WARP, stolen via a warp-local atomic (no
// barriers, no CTA coupling — round-16's lockstep regression avoided).
__global__ void __launch_bounds__(256, 2)
k_mlp(const int* __restrict__ knn,
      const float* __restrict__ W3b, const float* __restrict__ b3b,
      float* __restrict__ out) {
    extern __shared__ char smem[];
    float* sW  = (float*)(smem + OFF_WB);
    float* sBb = (float*)(smem + OFF_BB);
    const int tid  = threadIdx.x;
    const int wid  = tid >> 5;
    const int lane = tid & 31;

    // prologue: inputs only (runs under PDL overlap)
    for (int idx = tid; idx < 16384; idx += 256) {
        int k = idx >> 7, n = idx & 127;
        uint32_t v = to_tf32(__ldg(&W3b[k * DIM + n]));
        sW[n * RSF + k] = __uint_as_float(v);
    }
    if (tid < 128) sBb[tid] = __ldg(&b3b[tid]);
    __syncthreads();

    const int qr = lane >> 2;            // fragment row group (0..7)
    const int qc = (lane & 3) * 2;       // output col pair in n8-tile
    const int q4 = (lane & 3) * 4;       // contiguous k base
    const float* wB = sW + (size_t)qr * RSF + q4;
    const unsigned int nStatic = gridDim.x * 8u;   // statically assigned points

    int i = blockIdx.x * 8 + wid;        // this warp's first point (static)
    int jj = __ldg(&knn[i * KNB + (lane & 15)]);

    cudaGridDependencySynchronize();     // wait for k_uc's g_u/g_cc writes

    const float* u0;
    const float* u1;
    const float* cp;
    {
        const int j0 = __shfl_sync(0xFFFFFFFF, jj, qr);
        const int j1 = __shfl_sync(0xFFFFFFFF, jj, qr + 8);
        u0 = g_u  + (size_t)j0 * DIM + q4;
        u1 = g_u  + (size_t)j1 * DIM + q4;
        cp = g_cc + (size_t)i * DIM + q4;
    }
    float4 va = *(const float4*)(u0);
    float4 vb = *(const float4*)(u1);
    float4 vc = *(const float4*)(cp);

    while (true) {
        // warp-local steal of the next point (latency covered by the GEMM)
        unsigned int grab = 0;
        if (lane == 0) grab = nStatic + atomicAdd(&g_ptCtr, 1u);
        const int inext = (int)__shfl_sync(0xFFFFFFFF, grab, 0);

        int jjn = 0;
        if (inext < NPTS) jjn = __ldg(&knn[inext * KNB + (lane & 15)]);

        float acc[16][4];
#pragma unroll
        for (int t = 0; t < 16; t++) { acc[t][0] = acc[t][1] = acc[t][2] = acc[t][3] = 0.f; }

#pragma unroll
        for (int ks = 0; ks < 8; ks++) {
            float4 na, nb, nc;
            if (ks < 7) {
                const int kb = (ks + 1) * 16;
                na = *(const float4*)(u0 + kb);
                nb = *(const float4*)(u1 + kb);
                nc = *(const float4*)(cp + kb);
            } else {
                const int j0n = __shfl_sync(0xFFFFFFFF, jjn, qr);
                const int j1n = __shfl_sync(0xFFFFFFFF, jjn, qr + 8);
                const int isafe = (inext < NPTS) ? inext : 0;
                u0 = g_u  + (size_t)j0n * DIM + q4;
                u1 = g_u  + (size_t)j1n * DIM + q4;
                cp = g_cc + (size_t)isafe * DIM + q4;
                na = *(const float4*)(u0);
                nb = *(const float4*)(u1);
                nc = *(const float4*)(cp);
            }

            // h = gelu(u + cc) for data-k {4c..4c+3}, rows j0 / j1
            uint32_t a00 = to_tf32(gelu_fast(va.x + vc.x));
            uint32_t a01 = to_tf32(gelu_fast(va.y + vc.y));
            uint32_t a02 = to_tf32(gelu_fast(va.z + vc.z));
            uint32_t a03 = to_tf32(gelu_fast(va.w + vc.w));
            uint32_t a10 = to_tf32(gelu_fast(vb.x + vc.x));
            uint32_t a11 = to_tf32(gelu_fast(vb.y + vc.y));
            uint32_t a12 = to_tf32(gelu_fast(vb.z + vc.z));
            uint32_t a13 = to_tf32(gelu_fast(vb.w + vc.w));

            const float* wk = wB + ks * 16;
#pragma unroll
            for (int nt = 0; nt < 16; nt++) {
                float4 w = *(const float4*)(wk + (size_t)nt * 8 * RSF);
                mma_tf32(acc[nt], a00, a10, a01, a11,
                         __float_as_uint(w.x), __float_as_uint(w.y));
                mma_tf32(acc[nt], a02, a12, a03, a13,
                         __float_as_uint(w.z), __float_as_uint(w.w));
            }
            va = na; vb = nb; vc = nc;
        }

        // ---- epilogue: +b3b, store ----
        {
            float* obase = out + ((size_t)i * KNB) * DIM;
#pragma unroll
            for (int nt = 0; nt < 16; nt++) {
                int c = nt * 8 + qc;
                float bb0 = sBb[c], bb1 = sBb[c + 1];
                *(float2*)(obase + (size_t)qr * DIM + c) =
                    make_float2(acc[nt][0] + bb0, acc[nt][1] + bb1);
                *(float2*)(obase + (size_t)(qr + 8) * DIM + c) =
                    make_float2(acc[nt][2] + bb0, acc[nt][3] + bb1);
            }
        }
        if (inext >= NPTS) break;
        i = inext;
        jj = jjn;
    }
}

// ---------------- launch ----------------
extern "C" void kernel_launch(void* const* d_in, const int* in_sizes, int n_in,
                              void* d_out, int out_size) {
    const float* xyz = (const float*)d_in[0];
    const int*   knn = (const int*)d_in[1];
    const float* W1  = (const float*)d_in[2];
    const float* b1  = (const float*)d_in[3];
    const float* W2  = (const float*)d_in[4];
    const float* b2  = (const float*)d_in[5];
    const float* W3a = (const float*)d_in[6];
    const float* b3a = (const float*)d_in[7];
    const float* W3b = (const float*)d_in[8];
    const float* b3b = (const float*)d_in[9];
    float* out = (float*)d_out;

    cudaFuncSetAttribute(k_uc, cudaFuncAttributeMaxDynamicSharedMemorySize, UC_SMEM_BYTES);
    cudaFuncSetAttribute(k_mlp, cudaFuncAttributeMaxDynamicSharedMemorySize, SMEM_BYTES);

    int dev = 0, sms = 148;
    cudaGetDevice(&dev);
    cudaDeviceGetAttribute(&sms, cudaDevAttrMultiProcessorCount, dev);

    k_p01<<<NPTS / 16, 256>>>(xyz, W1, b1, W2, b2);

    cudaLaunchAttribute attr[1];
    attr[0].id = cudaLaunchAttributeProgrammaticStreamSerialization;
    attr[0].val.programmaticStreamSerializationAllowed = 1;

    {   // k_uc with PDL (prologue overlaps k_p01 tail)
        cudaLaunchConfig_t cfg = {};
        cfg.gridDim = dim3(NPTS / 16, 1, 1);
        cfg.blockDim = dim3(256, 1, 1);
        cfg.dynamicSmemBytes = UC_SMEM_BYTES;
        cfg.stream = 0;
        cfg.attrs = attr;
        cfg.numAttrs = 1;
        cudaLaunchKernelEx(&cfg, k_uc, knn, W3a, b3a);
    }
    {   // k_mlp with PDL (W transpose overlaps k_uc tail)
        cudaLaunchConfig_t cfg = {};
        cfg.gridDim = dim3(2 * sms, 1, 1);
        cfg.blockDim = dim3(256, 1, 1);
        cfg.dynamicSmemBytes = SMEM_BYTES;
        cfg.stream = 0;
        cfg.attrs = attr;
        cfg.numAttrs = 1;
        cudaLaunchKernelEx(&cfg, k_mlp, knn, W3b, b3b, out);
    }
}